// round 15
// baseline (speedup 1.0000x reference)
#include <cuda_runtime.h>
#include <cuda_bf16.h>
#include <math.h>
#include <stdint.h>

// Problem shape (fixed by the reference): B=4096, D=512
#define BSZ 4096
#define DK  512
#define NT  32              // 4096/128 tiles per dim
#define KC  32              // K-chunk (fp32 elems)
#define NCHUNK (DK/KC)      // 16
#define TB 8192             // one operand tile: 128 rows x 32 bf16 x 2B
#define STAGE (4*TB)        // Ah, Al, Bh, Bl per chunk = 32KB
#define DSMEM (2*STAGE)     // double-buffered = 64KB

// ---------------------------------------------------------------------------
// Static device scratch (allocation-free rule)
// ---------------------------------------------------------------------------
__device__ float g_prow_m[NT * BSZ];
__device__ float g_prow_s[NT * BSZ];
__device__ float g_pcol_m[NT * BSZ];
__device__ float g_pcol_s[NT * BSZ];
__device__ float g_lse[2 * BSZ];
__device__ float g_diag[BSZ];

// ---------------------------------------------------------------------------
// PTX helpers — base-target-safe (NO tcgen05: harness targets sm_103, not 103a)
// ---------------------------------------------------------------------------
__device__ __forceinline__ uint32_t smem_to_u32(const void* p) {
    uint32_t a;
    asm("{ .reg .u64 t; cvta.to.shared.u64 t, %1; cvt.u32.u64 %0, t; }" : "=r"(a) : "l"(p));
    return a;
}
__device__ __forceinline__ void ldsm_x4(uint32_t& r0, uint32_t& r1, uint32_t& r2,
                                        uint32_t& r3, uint32_t addr) {
    asm volatile("ldmatrix.sync.aligned.m8n8.x4.shared.b16 {%0,%1,%2,%3}, [%4];"
                 : "=r"(r0), "=r"(r1), "=r"(r2), "=r"(r3) : "r"(addr));
}
__device__ __forceinline__ void mma16816(float* d, const uint32_t* a, uint32_t b0, uint32_t b1) {
    asm volatile(
        "mma.sync.aligned.m16n8k16.row.col.f32.bf16.bf16.f32 "
        "{%0,%1,%2,%3}, {%4,%5,%6,%7}, {%8,%9}, {%0,%1,%2,%3};"
        : "+f"(d[0]), "+f"(d[1]), "+f"(d[2]), "+f"(d[3])
        : "r"(a[0]), "r"(a[1]), "r"(a[2]), "r"(a[3]), "r"(b0), "r"(b1));
}
// Split two float4 (8 fp32) into 8 bf16 hi + 8 bf16 lo (uint4 each)
__device__ __forceinline__ void split8(const float4& x, const float4& y, uint4& h, uint4& l) {
    __nv_bfloat162 h0 = __floats2bfloat162_rn(x.x, x.y);
    __nv_bfloat162 h1 = __floats2bfloat162_rn(x.z, x.w);
    __nv_bfloat162 h2 = __floats2bfloat162_rn(y.x, y.y);
    __nv_bfloat162 h3 = __floats2bfloat162_rn(y.z, y.w);
    __nv_bfloat162 l0 = __floats2bfloat162_rn(x.x - __low2float(h0), x.y - __high2float(h0));
    __nv_bfloat162 l1 = __floats2bfloat162_rn(x.z - __low2float(h1), x.w - __high2float(h1));
    __nv_bfloat162 l2 = __floats2bfloat162_rn(y.x - __low2float(h2), y.y - __high2float(h2));
    __nv_bfloat162 l3 = __floats2bfloat162_rn(y.z - __low2float(h3), y.w - __high2float(h3));
    h.x = *reinterpret_cast<uint32_t*>(&h0); h.y = *reinterpret_cast<uint32_t*>(&h1);
    h.z = *reinterpret_cast<uint32_t*>(&h2); h.w = *reinterpret_cast<uint32_t*>(&h3);
    l.x = *reinterpret_cast<uint32_t*>(&l0); l.y = *reinterpret_cast<uint32_t*>(&l1);
    l.z = *reinterpret_cast<uint32_t*>(&l2); l.w = *reinterpret_cast<uint32_t*>(&l3);
}

// ---------------------------------------------------------------------------
// Kernel 1: split-bf16 HMMA 128x128 logits tile + fused row/col (max,sumexp)
// partials reduced straight out of the MMA accumulator fragments.
//   grid (NT, NT), 256 threads = 8 warps in 2(M) x 4(N); warp tile 64x32.
// ---------------------------------------------------------------------------
__global__ __launch_bounds__(256, 1)
void gemm_lse_mma(const float* __restrict__ A, const float* __restrict__ Bm,
                  const float* __restrict__ p_log_tau)
{
    extern __shared__ __align__(1024) char dsm[];
    __shared__ float RowM[4][128], RowS[4][128];   // by wn
    __shared__ float ColM[2][128], ColS[2][128];   // by wm

    const int tid  = threadIdx.x;
    const int wid  = tid >> 5;
    const int lane = tid & 31;
    const int wm   = wid >> 2;     // 0..1  (M: 64-row slab)
    const int wn   = wid & 3;      // 0..3  (N: 32-col slab)
    const int q    = lane >> 2;    // 0..7
    const int tg   = lane & 3;     // 0..3
    const int bi   = blockIdx.y;
    const int bj   = blockIdx.x;
    const uint32_t dsm_u = smem_to_u32(dsm);

    float acc[4][4][4];
#pragma unroll
    for (int i = 0; i < 4; i++)
#pragma unroll
        for (int j = 0; j < 4; j++)
#pragma unroll
            for (int e = 0; e < 4; e++) acc[i][j][e] = 0.0f;

    // ---- global load mapping: thread -> (row, 16-float half of the 32-float chunk)
    const int r    = tid >> 1;
    const int half = tid & 1;
    const float4* Ag = reinterpret_cast<const float4*>(A  + (size_t)(bi * 128 + r) * DK + half * 16);
    const float4* Bg = reinterpret_cast<const float4*>(Bm + (size_t)(bj * 128 + r) * DK + half * 16);

    // ---- swizzled smem store offsets (SW64-ish: seg ^ ((row>>1)&3), 64B rows)
    const int key   = (r >> 1) & 3;
    const int soff0 = r * 64 + (((half * 2 + 0) ^ key) << 4);
    const int soff1 = r * 64 + (((half * 2 + 1) ^ key) << 4);

    // ---- A-fragment ldmatrix addresses (per fm, per kstep): row/kseg per lane
    const int arow_lo = (lane & 15);         // + wm*64 + fm*16
    const int a_ksel  = lane >> 4;           // 0/1 -> kseg within k16
    // ---- B-fragment ldmatrix addresses (x4 covers n16 x k16 = 2 frags)
    const int m4      = lane >> 3;           // 0..3 matrix id
    const int brow_lo = ((m4 >> 1) << 3) + (lane & 7);  // + wn*32 + p*16
    const int b_ksel  = m4 & 1;

    float4 va[4], vb[4];
#pragma unroll
    for (int j = 0; j < 4; j++) { va[j] = Ag[j]; vb[j] = Bg[j]; }
    {   // store chunk 0 -> buffer 0
        uint4 h, l;
        char* dst = dsm;
        split8(va[0], va[1], h, l);
        *reinterpret_cast<uint4*>(dst + 0 * TB + soff0) = h;
        *reinterpret_cast<uint4*>(dst + 1 * TB + soff0) = l;
        split8(va[2], va[3], h, l);
        *reinterpret_cast<uint4*>(dst + 0 * TB + soff1) = h;
        *reinterpret_cast<uint4*>(dst + 1 * TB + soff1) = l;
        split8(vb[0], vb[1], h, l);
        *reinterpret_cast<uint4*>(dst + 2 * TB + soff0) = h;
        *reinterpret_cast<uint4*>(dst + 3 * TB + soff0) = l;
        split8(vb[2], vb[3], h, l);
        *reinterpret_cast<uint4*>(dst + 2 * TB + soff1) = h;
        *reinterpret_cast<uint4*>(dst + 3 * TB + soff1) = l;
    }
    __syncthreads();

    for (int c = 0; c < NCHUNK; ++c) {
        const uint32_t sb = dsm_u + (uint32_t)(c & 1) * STAGE;

        if (c + 1 < NCHUNK) {
#pragma unroll
            for (int j = 0; j < 4; j++) {
                va[j] = Ag[(c + 1) * 8 + j];
                vb[j] = Bg[(c + 1) * 8 + j];
            }
        }

        // ---- compute: 2 k16-steps on this buffer
#pragma unroll
        for (int ks = 0; ks < 2; ++ks) {
            uint32_t ahi[4][4], alo[4][4], bhi[4][2], blo[4][2];
#pragma unroll
            for (int fm = 0; fm < 4; fm++) {
                int row  = wm * 64 + fm * 16 + arow_lo;
                int kseg = ks * 2 + a_ksel;
                uint32_t off = (uint32_t)(row * 64 + (((kseg) ^ ((row >> 1) & 3)) << 4));
                ldsm_x4(ahi[fm][0], ahi[fm][1], ahi[fm][2], ahi[fm][3], sb + 0 * TB + off);
                ldsm_x4(alo[fm][0], alo[fm][1], alo[fm][2], alo[fm][3], sb + 1 * TB + off);
            }
#pragma unroll
            for (int p = 0; p < 2; p++) {
                int row  = wn * 32 + p * 16 + brow_lo;
                int kseg = ks * 2 + b_ksel;
                uint32_t off = (uint32_t)(row * 64 + (((kseg) ^ ((row >> 1) & 3)) << 4));
                uint32_t t0, t1, t2, t3;
                ldsm_x4(t0, t1, t2, t3, sb + 2 * TB + off);
                bhi[p * 2][0] = t0; bhi[p * 2][1] = t1;
                bhi[p * 2 + 1][0] = t2; bhi[p * 2 + 1][1] = t3;
                ldsm_x4(t0, t1, t2, t3, sb + 3 * TB + off);
                blo[p * 2][0] = t0; blo[p * 2][1] = t1;
                blo[p * 2 + 1][0] = t2; blo[p * 2 + 1][1] = t3;
            }
#pragma unroll
            for (int fm = 0; fm < 4; fm++)
#pragma unroll
                for (int fn = 0; fn < 4; fn++) {
                    mma16816(acc[fm][fn], ahi[fm], bhi[fn][0], bhi[fn][1]);
                    mma16816(acc[fm][fn], ahi[fm], blo[fn][0], blo[fn][1]);
                    mma16816(acc[fm][fn], alo[fm], bhi[fn][0], bhi[fn][1]);
                }
        }

        // ---- stage chunk c+1 into the other buffer
        if (c + 1 < NCHUNK) {
            uint4 h, l;
            char* dst = dsm + ((c + 1) & 1) * STAGE;
            split8(va[0], va[1], h, l);
            *reinterpret_cast<uint4*>(dst + 0 * TB + soff0) = h;
            *reinterpret_cast<uint4*>(dst + 1 * TB + soff0) = l;
            split8(va[2], va[3], h, l);
            *reinterpret_cast<uint4*>(dst + 0 * TB + soff1) = h;
            *reinterpret_cast<uint4*>(dst + 1 * TB + soff1) = l;
            split8(vb[0], vb[1], h, l);
            *reinterpret_cast<uint4*>(dst + 2 * TB + soff0) = h;
            *reinterpret_cast<uint4*>(dst + 3 * TB + soff0) = l;
            split8(vb[2], vb[3], h, l);
            *reinterpret_cast<uint4*>(dst + 2 * TB + soff1) = h;
            *reinterpret_cast<uint4*>(dst + 3 * TB + soff1) = l;
        }
        __syncthreads();
    }

    // ------------------- epilogue: partials from fragments -------------------
    const float tau = fminf(expf(*p_log_tau), 100.0f);
#pragma unroll
    for (int fm = 0; fm < 4; fm++)
#pragma unroll
        for (int fn = 0; fn < 4; fn++)
#pragma unroll
            for (int e = 0; e < 4; e++) acc[fm][fn][e] *= tau;

    // Fragment element (fm,fn,e): row = wm*64+fm*16+q+(e>>1)*8, col = wn*32+fn*8+tg*2+(e&1)

    // ---- row partials: 8 cols local, merge across tg lanes (xor 1,2)
#pragma unroll
    for (int fm = 0; fm < 4; fm++) {
#pragma unroll
        for (int rh = 0; rh < 2; rh++) {
            float m = -3.4e38f;
#pragma unroll
            for (int fn = 0; fn < 4; fn++) {
                m = fmaxf(m, acc[fm][fn][rh * 2]);
                m = fmaxf(m, acc[fm][fn][rh * 2 + 1]);
            }
            float s = 0.0f;
#pragma unroll
            for (int fn = 0; fn < 4; fn++) {
                s += __expf(acc[fm][fn][rh * 2]     - m);
                s += __expf(acc[fm][fn][rh * 2 + 1] - m);
            }
#pragma unroll
            for (int o = 1; o < 4; o <<= 1) {
                float m2 = __shfl_xor_sync(0xffffffffu, m, o);
                float s2 = __shfl_xor_sync(0xffffffffu, s, o);
                float mo = fmaxf(m, m2);
                s = s * __expf(m - mo) + s2 * __expf(m2 - mo);
                m = mo;
            }
            if (tg == 0) {
                int rloc = wm * 64 + fm * 16 + rh * 8 + q;
                RowM[wn][rloc] = m;
                RowS[wn][rloc] = s;
            }
        }
    }

    // ---- col partials: 8 rows local, merge across q lanes (xor 4,8,16)
#pragma unroll
    for (int fn = 0; fn < 4; fn++) {
#pragma unroll
        for (int sub = 0; sub < 2; sub++) {
            float m = -3.4e38f;
#pragma unroll
            for (int fm = 0; fm < 4; fm++) {
                m = fmaxf(m, acc[fm][fn][sub]);
                m = fmaxf(m, acc[fm][fn][2 + sub]);
            }
            float s = 0.0f;
#pragma unroll
            for (int fm = 0; fm < 4; fm++) {
                s += __expf(acc[fm][fn][sub]     - m);
                s += __expf(acc[fm][fn][2 + sub] - m);
            }
#pragma unroll
            for (int o = 4; o < 32; o <<= 1) {
                float m2 = __shfl_xor_sync(0xffffffffu, m, o);
                float s2 = __shfl_xor_sync(0xffffffffu, s, o);
                float mo = fmaxf(m, m2);
                s = s * __expf(m - mo) + s2 * __expf(m2 - mo);
                m = mo;
            }
            if (q == 0) {
                int cloc = wn * 32 + fn * 8 + tg * 2 + sub;
                ColM[wm][cloc] = m;
                ColS[wm][cloc] = s;
            }
        }
    }
    __syncthreads();

    // ---- cross-warp merge + write global partials
    if (tid < 128) {
        float m = RowM[0][tid], s = RowS[0][tid];
#pragma unroll
        for (int w = 1; w < 4; w++) {
            float m2 = RowM[w][tid], s2 = RowS[w][tid];
            float mo = fmaxf(m, m2);
            s = s * __expf(m - mo) + s2 * __expf(m2 - mo);
            m = mo;
        }
        g_prow_m[bj * BSZ + bi * 128 + tid] = m;
        g_prow_s[bj * BSZ + bi * 128 + tid] = s;

        float cm = ColM[0][tid], cs = ColS[0][tid];
        {
            float m2 = ColM[1][tid], s2 = ColS[1][tid];
            float mo = fmaxf(cm, m2);
            cs = cs * __expf(cm - mo) + s2 * __expf(m2 - mo);
            cm = mo;
        }
        g_pcol_m[bi * BSZ + bj * 128 + tid] = cm;
        g_pcol_s[bi * BSZ + bj * 128 + tid] = cs;
    }
}

// ---------------------------------------------------------------------------
// Kernel 2: diagonal terms d_i = tau * dot(A_i, B_i) in full fp32
// ---------------------------------------------------------------------------
__global__ void diag_kernel(const float* __restrict__ A,
                            const float* __restrict__ Bm,
                            const float* __restrict__ p_log_tau)
{
    int gt   = blockIdx.x * blockDim.x + threadIdx.x;
    int w    = gt >> 5;
    int lane = threadIdx.x & 31;
    if (w >= BSZ) return;

    const float4* a = reinterpret_cast<const float4*>(A  + (size_t)w * DK);
    const float4* b = reinterpret_cast<const float4*>(Bm + (size_t)w * DK);
    float sum = 0.0f;
#pragma unroll
    for (int it = 0; it < 4; it++) {
        float4 x = a[it * 32 + lane];
        float4 y = b[it * 32 + lane];
        sum += x.x * y.x + x.y * y.y + x.z * y.z + x.w * y.w;
    }
#pragma unroll
    for (int o = 16; o > 0; o >>= 1) sum += __shfl_xor_sync(0xffffffffu, sum, o);

    if (lane == 0) {
        float tau = fminf(expf(*p_log_tau), 100.0f);
        g_diag[w] = tau * sum;
    }
}

// ---------------------------------------------------------------------------
// Kernel 3: finalize LSE per row / column from NT partials
// ---------------------------------------------------------------------------
__global__ void finalize_kernel()
{
    int t = blockIdx.x * blockDim.x + threadIdx.x;   // [0, 2B)
    if (t >= 2 * BSZ) return;
    const float* pm = (t < BSZ) ? g_prow_m : g_pcol_m;
    const float* ps = (t < BSZ) ? g_prow_s : g_pcol_s;
    int r = t & (BSZ - 1);

    float m = pm[r];
    float s = ps[r];
#pragma unroll 4
    for (int j = 1; j < NT; j++) {
        float m2 = pm[j * BSZ + r];
        float s2 = ps[j * BSZ + r];
        float mo = fmaxf(m, m2);
        s = s * __expf(m - mo) + s2 * __expf(m2 - mo);
        m = mo;
    }
    g_lse[t] = m + logf(s);
}

// ---------------------------------------------------------------------------
// Kernel 4: deterministic final fp64 reduction (1024 threads, fixed tree)
// ---------------------------------------------------------------------------
__global__ void reduce_kernel(float* __restrict__ out)
{
    __shared__ double sm[1024];
    int t = threadIdx.x;
    double a = 0.0;
#pragma unroll
    for (int i = 0; i < 8; i++) a += (double)g_lse[t + i * 1024];
#pragma unroll
    for (int i = 0; i < 4; i++) a -= 2.0 * (double)g_diag[t + i * 1024];
    sm[t] = a;
    __syncthreads();
    for (int o = 512; o > 0; o >>= 1) {
        if (t < o) sm[t] += sm[t + o];
        __syncthreads();
    }
    if (t == 0) out[0] = (float)(sm[0] / (2.0 * (double)BSZ));
}

// ---------------------------------------------------------------------------
// Inputs: 0=out_ftir f32[4096*512], 1=out_raman f32[4096*512],
// 2=labels i64[4096] (unused), 3=log_tau f32[1]. Output: 1 float.
// ---------------------------------------------------------------------------
extern "C" void kernel_launch(void* const* d_in, const int* in_sizes, int n_in,
                              void* d_out, int out_size)
{
    (void)in_sizes; (void)n_in; (void)out_size;
    const float* A  = (const float*)d_in[0];
    const float* Bm = (const float*)d_in[1];
    const float* lt = (const float*)d_in[3];
    float* out = (float*)d_out;

    cudaFuncSetAttribute(gemm_lse_mma, cudaFuncAttributeMaxDynamicSharedMemorySize, DSMEM);

    dim3 grid(NT, NT);
    gemm_lse_mma<<<grid, 256, DSMEM>>>(A, Bm, lt);
    diag_kernel<<<BSZ * 32 / 256, 256>>>(A, Bm, lt);
    finalize_kernel<<<(2 * BSZ) / 256, 256>>>();
    reduce_kernel<<<1, 1024>>>(out);
}

// round 16
// speedup vs baseline: 1.0075x; 1.0075x over previous
#include <cuda_runtime.h>
#include <cuda_bf16.h>
#include <math.h>
#include <stdint.h>

// Problem shape (fixed by the reference): B=4096, D=512
#define BSZ 4096
#define DK  512
#define NT  32              // 4096/128 tiles per dim
#define KC  32              // K-chunk (fp32 elems)
#define NCHUNK (DK/KC)      // 16
#define TB 8192             // one operand tile: 128 rows x 32 bf16 x 2B
#define STAGE (4*TB)        // Ah, Al, Bh, Bl per chunk = 32KB
#define DSMEM (2*STAGE)     // double-buffered = 64KB

// ---------------------------------------------------------------------------
// Static device scratch (allocation-free rule)
// ---------------------------------------------------------------------------
__device__ float g_prow_m[NT * BSZ];
__device__ float g_prow_s[NT * BSZ];
__device__ float g_pcol_m[NT * BSZ];
__device__ float g_pcol_s[NT * BSZ];
__device__ float g_lse[2 * BSZ];
__device__ float g_diag[BSZ];

// ---------------------------------------------------------------------------
// PTX helpers — base-target-safe (NO tcgen05: harness targets sm_103, not 103a)
// ---------------------------------------------------------------------------
__device__ __forceinline__ uint32_t smem_to_u32(const void* p) {
    uint32_t a;
    asm("{ .reg .u64 t; cvta.to.shared.u64 t, %1; cvt.u32.u64 %0, t; }" : "=r"(a) : "l"(p));
    return a;
}
__device__ __forceinline__ void ldsm_x4(uint32_t& r0, uint32_t& r1, uint32_t& r2,
                                        uint32_t& r3, uint32_t addr) {
    asm volatile("ldmatrix.sync.aligned.m8n8.x4.shared.b16 {%0,%1,%2,%3}, [%4];"
                 : "=r"(r0), "=r"(r1), "=r"(r2), "=r"(r3) : "r"(addr));
}
__device__ __forceinline__ void mma16816(float* d, const uint32_t* a, uint32_t b0, uint32_t b1) {
    asm volatile(
        "mma.sync.aligned.m16n8k16.row.col.f32.bf16.bf16.f32 "
        "{%0,%1,%2,%3}, {%4,%5,%6,%7}, {%8,%9}, {%0,%1,%2,%3};"
        : "+f"(d[0]), "+f"(d[1]), "+f"(d[2]), "+f"(d[3])
        : "r"(a[0]), "r"(a[1]), "r"(a[2]), "r"(a[3]), "r"(b0), "r"(b1));
}
// Split two float4 (8 fp32) into 8 bf16 hi + 8 bf16 lo (uint4 each)
__device__ __forceinline__ void split8(const float4& x, const float4& y, uint4& h, uint4& l) {
    __nv_bfloat162 h0 = __floats2bfloat162_rn(x.x, x.y);
    __nv_bfloat162 h1 = __floats2bfloat162_rn(x.z, x.w);
    __nv_bfloat162 h2 = __floats2bfloat162_rn(y.x, y.y);
    __nv_bfloat162 h3 = __floats2bfloat162_rn(y.z, y.w);
    __nv_bfloat162 l0 = __floats2bfloat162_rn(x.x - __low2float(h0), x.y - __high2float(h0));
    __nv_bfloat162 l1 = __floats2bfloat162_rn(x.z - __low2float(h1), x.w - __high2float(h1));
    __nv_bfloat162 l2 = __floats2bfloat162_rn(y.x - __low2float(h2), y.y - __high2float(h2));
    __nv_bfloat162 l3 = __floats2bfloat162_rn(y.z - __low2float(h3), y.w - __high2float(h3));
    h.x = *reinterpret_cast<uint32_t*>(&h0); h.y = *reinterpret_cast<uint32_t*>(&h1);
    h.z = *reinterpret_cast<uint32_t*>(&h2); h.w = *reinterpret_cast<uint32_t*>(&h3);
    l.x = *reinterpret_cast<uint32_t*>(&l0); l.y = *reinterpret_cast<uint32_t*>(&l1);
    l.z = *reinterpret_cast<uint32_t*>(&l2); l.w = *reinterpret_cast<uint32_t*>(&l3);
}

// ---------------------------------------------------------------------------
// Kernel 1: split-bf16 HMMA 128x128 logits tile + fused row/col (max,sumexp)
// partials reduced straight out of the MMA accumulator fragments.
//   grid (NT, NT), 256 threads = 8 warps in 2(M) x 4(N); warp tile 64x32.
// ---------------------------------------------------------------------------
__global__ __launch_bounds__(256, 1)
void gemm_lse_mma(const float* __restrict__ A, const float* __restrict__ Bm,
                  const float* __restrict__ p_log_tau)
{
    extern __shared__ __align__(1024) char dsm[];
    __shared__ float RowM[4][128], RowS[4][128];   // by wn
    __shared__ float ColM[2][128], ColS[2][128];   // by wm

    const int tid  = threadIdx.x;
    const int wid  = tid >> 5;
    const int lane = tid & 31;
    const int wm   = wid >> 2;     // 0..1  (M: 64-row slab)
    const int wn   = wid & 3;      // 0..3  (N: 32-col slab)
    const int q    = lane >> 2;    // 0..7
    const int tg   = lane & 3;     // 0..3
    const int bi   = blockIdx.y;
    const int bj   = blockIdx.x;
    const uint32_t dsm_u = smem_to_u32(dsm);

    float acc[4][4][4];
#pragma unroll
    for (int i = 0; i < 4; i++)
#pragma unroll
        for (int j = 0; j < 4; j++)
#pragma unroll
            for (int e = 0; e < 4; e++) acc[i][j][e] = 0.0f;

    // ---- global load mapping: thread -> (row, 16-float half of the 32-float chunk)
    const int r    = tid >> 1;
    const int half = tid & 1;
    const float4* Ag = reinterpret_cast<const float4*>(A  + (size_t)(bi * 128 + r) * DK + half * 16);
    const float4* Bg = reinterpret_cast<const float4*>(Bm + (size_t)(bj * 128 + r) * DK + half * 16);

    // ---- swizzled smem store offsets (SW64-ish: seg ^ ((row>>1)&3), 64B rows)
    const int key   = (r >> 1) & 3;
    const int soff0 = r * 64 + (((half * 2 + 0) ^ key) << 4);
    const int soff1 = r * 64 + (((half * 2 + 1) ^ key) << 4);

    // ---- A-fragment ldmatrix addresses (per fm, per kstep): row/kseg per lane
    const int arow_lo = (lane & 15);         // + wm*64 + fm*16
    const int a_ksel  = lane >> 4;           // 0/1 -> kseg within k16
    // ---- B-fragment ldmatrix addresses (x4 covers n16 x k16 = 2 frags)
    const int m4      = lane >> 3;           // 0..3 matrix id
    const int brow_lo = ((m4 >> 1) << 3) + (lane & 7);  // + wn*32 + p*16
    const int b_ksel  = m4 & 1;

    float4 va[4], vb[4];
#pragma unroll
    for (int j = 0; j < 4; j++) { va[j] = Ag[j]; vb[j] = Bg[j]; }
    {   // store chunk 0 -> buffer 0
        uint4 h, l;
        char* dst = dsm;
        split8(va[0], va[1], h, l);
        *reinterpret_cast<uint4*>(dst + 0 * TB + soff0) = h;
        *reinterpret_cast<uint4*>(dst + 1 * TB + soff0) = l;
        split8(va[2], va[3], h, l);
        *reinterpret_cast<uint4*>(dst + 0 * TB + soff1) = h;
        *reinterpret_cast<uint4*>(dst + 1 * TB + soff1) = l;
        split8(vb[0], vb[1], h, l);
        *reinterpret_cast<uint4*>(dst + 2 * TB + soff0) = h;
        *reinterpret_cast<uint4*>(dst + 3 * TB + soff0) = l;
        split8(vb[2], vb[3], h, l);
        *reinterpret_cast<uint4*>(dst + 2 * TB + soff1) = h;
        *reinterpret_cast<uint4*>(dst + 3 * TB + soff1) = l;
    }
    __syncthreads();

    for (int c = 0; c < NCHUNK; ++c) {
        const uint32_t sb = dsm_u + (uint32_t)(c & 1) * STAGE;

        if (c + 1 < NCHUNK) {
#pragma unroll
            for (int j = 0; j < 4; j++) {
                va[j] = Ag[(c + 1) * 8 + j];
                vb[j] = Bg[(c + 1) * 8 + j];
            }
        }

        // ---- compute: 2 k16-steps on this buffer
#pragma unroll
        for (int ks = 0; ks < 2; ++ks) {
            uint32_t ahi[4][4], alo[4][4], bhi[4][2], blo[4][2];
#pragma unroll
            for (int fm = 0; fm < 4; fm++) {
                int row  = wm * 64 + fm * 16 + arow_lo;
                int kseg = ks * 2 + a_ksel;
                uint32_t off = (uint32_t)(row * 64 + (((kseg) ^ ((row >> 1) & 3)) << 4));
                ldsm_x4(ahi[fm][0], ahi[fm][1], ahi[fm][2], ahi[fm][3], sb + 0 * TB + off);
                ldsm_x4(alo[fm][0], alo[fm][1], alo[fm][2], alo[fm][3], sb + 1 * TB + off);
            }
#pragma unroll
            for (int p = 0; p < 2; p++) {
                int row  = wn * 32 + p * 16 + brow_lo;
                int kseg = ks * 2 + b_ksel;
                uint32_t off = (uint32_t)(row * 64 + (((kseg) ^ ((row >> 1) & 3)) << 4));
                uint32_t t0, t1, t2, t3;
                ldsm_x4(t0, t1, t2, t3, sb + 2 * TB + off);
                bhi[p * 2][0] = t0; bhi[p * 2][1] = t1;
                bhi[p * 2 + 1][0] = t2; bhi[p * 2 + 1][1] = t3;
                ldsm_x4(t0, t1, t2, t3, sb + 3 * TB + off);
                blo[p * 2][0] = t0; blo[p * 2][1] = t1;
                blo[p * 2 + 1][0] = t2; blo[p * 2 + 1][1] = t3;
            }
#pragma unroll
            for (int fm = 0; fm < 4; fm++)
#pragma unroll
                for (int fn = 0; fn < 4; fn++) {
                    mma16816(acc[fm][fn], ahi[fm], bhi[fn][0], bhi[fn][1]);
                    mma16816(acc[fm][fn], ahi[fm], blo[fn][0], blo[fn][1]);
                    mma16816(acc[fm][fn], alo[fm], bhi[fn][0], bhi[fn][1]);
                }
        }

        // ---- stage chunk c+1 into the other buffer
        if (c + 1 < NCHUNK) {
            uint4 h, l;
            char* dst = dsm + ((c + 1) & 1) * STAGE;
            split8(va[0], va[1], h, l);
            *reinterpret_cast<uint4*>(dst + 0 * TB + soff0) = h;
            *reinterpret_cast<uint4*>(dst + 1 * TB + soff0) = l;
            split8(va[2], va[3], h, l);
            *reinterpret_cast<uint4*>(dst + 0 * TB + soff1) = h;
            *reinterpret_cast<uint4*>(dst + 1 * TB + soff1) = l;
            split8(vb[0], vb[1], h, l);
            *reinterpret_cast<uint4*>(dst + 2 * TB + soff0) = h;
            *reinterpret_cast<uint4*>(dst + 3 * TB + soff0) = l;
            split8(vb[2], vb[3], h, l);
            *reinterpret_cast<uint4*>(dst + 2 * TB + soff1) = h;
            *reinterpret_cast<uint4*>(dst + 3 * TB + soff1) = l;
        }
        __syncthreads();
    }

    // ------------------- epilogue: partials from fragments -------------------
    const float tau = fminf(expf(*p_log_tau), 100.0f);
#pragma unroll
    for (int fm = 0; fm < 4; fm++)
#pragma unroll
        for (int fn = 0; fn < 4; fn++)
#pragma unroll
            for (int e = 0; e < 4; e++) acc[fm][fn][e] *= tau;

    // Fragment element (fm,fn,e): row = wm*64+fm*16+q+(e>>1)*8, col = wn*32+fn*8+tg*2+(e&1)

    // ---- row partials: 8 cols local, merge across tg lanes (xor 1,2)
#pragma unroll
    for (int fm = 0; fm < 4; fm++) {
#pragma unroll
        for (int rh = 0; rh < 2; rh++) {
            float m = -3.4e38f;
#pragma unroll
            for (int fn = 0; fn < 4; fn++) {
                m = fmaxf(m, acc[fm][fn][rh * 2]);
                m = fmaxf(m, acc[fm][fn][rh * 2 + 1]);
            }
            float s = 0.0f;
#pragma unroll
            for (int fn = 0; fn < 4; fn++) {
                s += __expf(acc[fm][fn][rh * 2]     - m);
                s += __expf(acc[fm][fn][rh * 2 + 1] - m);
            }
#pragma unroll
            for (int o = 1; o < 4; o <<= 1) {
                float m2 = __shfl_xor_sync(0xffffffffu, m, o);
                float s2 = __shfl_xor_sync(0xffffffffu, s, o);
                float mo = fmaxf(m, m2);
                s = s * __expf(m - mo) + s2 * __expf(m2 - mo);
                m = mo;
            }
            if (tg == 0) {
                int rloc = wm * 64 + fm * 16 + rh * 8 + q;
                RowM[wn][rloc] = m;
                RowS[wn][rloc] = s;
            }
        }
    }

    // ---- col partials: 8 rows local, merge across q lanes (xor 4,8,16)
#pragma unroll
    for (int fn = 0; fn < 4; fn++) {
#pragma unroll
        for (int sub = 0; sub < 2; sub++) {
            float m = -3.4e38f;
#pragma unroll
            for (int fm = 0; fm < 4; fm++) {
                m = fmaxf(m, acc[fm][fn][sub]);
                m = fmaxf(m, acc[fm][fn][2 + sub]);
            }
            float s = 0.0f;
#pragma unroll
            for (int fm = 0; fm < 4; fm++) {
                s += __expf(acc[fm][fn][sub]     - m);
                s += __expf(acc[fm][fn][2 + sub] - m);
            }
#pragma unroll
            for (int o = 4; o < 32; o <<= 1) {
                float m2 = __shfl_xor_sync(0xffffffffu, m, o);
                float s2 = __shfl_xor_sync(0xffffffffu, s, o);
                float mo = fmaxf(m, m2);
                s = s * __expf(m - mo) + s2 * __expf(m2 - mo);
                m = mo;
            }
            if (q == 0) {
                int cloc = wn * 32 + fn * 8 + tg * 2 + sub;
                ColM[wm][cloc] = m;
                ColS[wm][cloc] = s;
            }
        }
    }
    __syncthreads();

    // ---- cross-warp merge + write global partials
    if (tid < 128) {
        float m = RowM[0][tid], s = RowS[0][tid];
#pragma unroll
        for (int w = 1; w < 4; w++) {
            float m2 = RowM[w][tid], s2 = RowS[w][tid];
            float mo = fmaxf(m, m2);
            s = s * __expf(m - mo) + s2 * __expf(m2 - mo);
            m = mo;
        }
        g_prow_m[bj * BSZ + bi * 128 + tid] = m;
        g_prow_s[bj * BSZ + bi * 128 + tid] = s;

        float cm = ColM[0][tid], cs = ColS[0][tid];
        {
            float m2 = ColM[1][tid], s2 = ColS[1][tid];
            float mo = fmaxf(cm, m2);
            cs = cs * __expf(cm - mo) + s2 * __expf(m2 - mo);
            cm = mo;
        }
        g_pcol_m[bi * BSZ + bj * 128 + tid] = cm;
        g_pcol_s[bi * BSZ + bj * 128 + tid] = cs;
    }
}

// ---------------------------------------------------------------------------
// Kernel 2: diagonal terms d_i = tau * dot(A_i, B_i) in full fp32
// ---------------------------------------------------------------------------
__global__ void diag_kernel(const float* __restrict__ A,
                            const float* __restrict__ Bm,
                            const float* __restrict__ p_log_tau)
{
    int gt   = blockIdx.x * blockDim.x + threadIdx.x;
    int w    = gt >> 5;
    int lane = threadIdx.x & 31;
    if (w >= BSZ) return;

    const float4* a = reinterpret_cast<const float4*>(A  + (size_t)w * DK);
    const float4* b = reinterpret_cast<const float4*>(Bm + (size_t)w * DK);
    float sum = 0.0f;
#pragma unroll
    for (int it = 0; it < 4; it++) {
        float4 x = a[it * 32 + lane];
        float4 y = b[it * 32 + lane];
        sum += x.x * y.x + x.y * y.y + x.z * y.z + x.w * y.w;
    }
#pragma unroll
    for (int o = 16; o > 0; o >>= 1) sum += __shfl_xor_sync(0xffffffffu, sum, o);

    if (lane == 0) {
        float tau = fminf(expf(*p_log_tau), 100.0f);
        g_diag[w] = tau * sum;
    }
}

// ---------------------------------------------------------------------------
// Kernel 3: finalize LSE per row / column from NT partials
// ---------------------------------------------------------------------------
__global__ void finalize_kernel()
{
    int t = blockIdx.x * blockDim.x + threadIdx.x;   // [0, 2B)
    if (t >= 2 * BSZ) return;
    const float* pm = (t < BSZ) ? g_prow_m : g_pcol_m;
    const float* ps = (t < BSZ) ? g_prow_s : g_pcol_s;
    int r = t & (BSZ - 1);

    float m = pm[r];
    float s = ps[r];
#pragma unroll 4
    for (int j = 1; j < NT; j++) {
        float m2 = pm[j * BSZ + r];
        float s2 = ps[j * BSZ + r];
        float mo = fmaxf(m, m2);
        s = s * __expf(m - mo) + s2 * __expf(m2 - mo);
        m = mo;
    }
    g_lse[t] = m + logf(s);
}

// ---------------------------------------------------------------------------
// Kernel 4: deterministic final fp64 reduction (1024 threads, fixed tree)
// ---------------------------------------------------------------------------
__global__ void reduce_kernel(float* __restrict__ out)
{
    __shared__ double sm[1024];
    int t = threadIdx.x;
    double a = 0.0;
#pragma unroll
    for (int i = 0; i < 8; i++) a += (double)g_lse[t + i * 1024];
#pragma unroll
    for (int i = 0; i < 4; i++) a -= 2.0 * (double)g_diag[t + i * 1024];
    sm[t] = a;
    __syncthreads();
    for (int o = 512; o > 0; o >>= 1) {
        if (t < o) sm[t] += sm[t + o];
        __syncthreads();
    }
    if (t == 0) out[0] = (float)(sm[0] / (2.0 * (double)BSZ));
}

// ---------------------------------------------------------------------------
// Inputs: 0=out_ftir f32[4096*512], 1=out_raman f32[4096*512],
// 2=labels i64[4096] (unused), 3=log_tau f32[1]. Output: 1 float.
// ---------------------------------------------------------------------------
extern "C" void kernel_launch(void* const* d_in, const int* in_sizes, int n_in,
                              void* d_out, int out_size)
{
    (void)in_sizes; (void)n_in; (void)out_size;
    const float* A  = (const float*)d_in[0];
    const float* Bm = (const float*)d_in[1];
    const float* lt = (const float*)d_in[3];
    float* out = (float*)d_out;

    cudaFuncSetAttribute(gemm_lse_mma, cudaFuncAttributeMaxDynamicSharedMemorySize, DSMEM);

    dim3 grid(NT, NT);
    gemm_lse_mma<<<grid, 256, DSMEM>>>(A, Bm, lt);
    diag_kernel<<<BSZ * 32 / 256, 256>>>(A, Bm, lt);
    finalize_kernel<<<(2 * BSZ) / 256, 256>>>();
    reduce_kernel<<<1, 1024>>>(out);
}